// round 11
// baseline (speedup 1.0000x reference)
#include <cuda_runtime.h>
#include <cuda_bf16.h>
#include <cuda_fp16.h>
#include <cstdint>

#define NN 131072
#define EE 2097152

// ---------------- device scratch (static; no allocation allowed) ----------------
__device__ float  g_dis[NN];           // degree accumulator -> rsqrt(deg)
__device__ int    g_cnt[NN];           // in-degree histogram
__device__ int    g_rowptr[NN];        // exclusive scan of g_cnt
__device__ int    g_cur[NN];           // scatter cursor
__device__ int    g_blksum[128];
__device__ int    g_blkoff[128];
__device__ int2   g_csr[EE];           // (src, __float_as_int(norm)), grouped by dst
__device__ __half g_xh[NN * 64];       // fp16 copy of x (one 128B line per node)
__device__ float  g_aggx[NN * 64];     // A_norm @ x  (fp32 for GEMM1)
__device__ float  g_h1[NN * 128];      // relu(agg(x) @ W1 + b1)
__device__ __half g_h2h[NN * 64];      // h1 @ W2  (fp16 for agg2 gathers)
__device__ float  g_h2[NN * 64];       // A_norm @ h2t (fp32 for FC)

// ---------------- init + degree/histogram ----------------
__global__ void k_init() {
    int i = blockIdx.x * blockDim.x + threadIdx.x;
    if (i < NN) { g_dis[i] = 1.0f; g_cnt[i] = 0; }   // self-loop weight = 1
}

__global__ void k_deg_hist(const int* __restrict__ ei, const float* __restrict__ ew) {
    int e = blockIdx.x * blockDim.x + threadIdx.x;
    if (e < EE) {
        int d = ei[EE + e];
        atomicAdd(&g_dis[d], ew[e]);
        atomicAdd(&g_cnt[d], 1);
    }
}

// ---------------- x -> fp16 (coalesced convert) ----------------
__global__ void k_x2h(const float* __restrict__ X) {
    int t = blockIdx.x * blockDim.x + threadIdx.x;   // NN*16 threads, float4 each
    if (t >= NN * 16) return;
    float4 v = ((const float4*)X)[t];
    __half2* O = (__half2*)g_xh;
    O[2 * t]     = __floats2half2_rn(v.x, v.y);
    O[2 * t + 1] = __floats2half2_rn(v.z, v.w);
}

// ---------------- exclusive scan of g_cnt (128 blocks x 1024 elems) ----------------
__global__ void k_scan1() {
    __shared__ int warp_s[8];
    int b = blockIdx.x, t = threadIdx.x;
    int base = b * 1024 + t * 4;
    int4 c = *(const int4*)&g_cnt[base];
    int s0 = c.x, s1 = s0 + c.y, s2 = s1 + c.z, s3 = s2 + c.w;
    int tsum = s3;
    int lane = t & 31, warp = t >> 5;
    int v = tsum;
    #pragma unroll
    for (int off = 1; off < 32; off <<= 1) {
        int u = __shfl_up_sync(0xffffffffu, v, off);
        if (lane >= off) v += u;
    }
    if (lane == 31) warp_s[warp] = v;
    __syncthreads();
    if (t < 8) {
        int x = warp_s[t];
        #pragma unroll
        for (int off = 1; off < 8; off <<= 1) {
            int u = __shfl_up_sync(0xffu, x, off);
            if (t >= off) x += u;
        }
        warp_s[t] = x;
    }
    __syncthreads();
    int woff = (warp > 0) ? warp_s[warp - 1] : 0;
    int texcl = woff + v - tsum;
    g_rowptr[base + 0] = texcl;
    g_rowptr[base + 1] = texcl + s0;
    g_rowptr[base + 2] = texcl + s1;
    g_rowptr[base + 3] = texcl + s2;
    if (t == 255) g_blksum[b] = woff + v;
}

__global__ void k_scan2() {
    __shared__ int sh[128];
    int t = threadIdx.x;
    int v = g_blksum[t];
    sh[t] = v;
    __syncthreads();
    for (int off = 1; off < 128; off <<= 1) {
        int u = (t >= off) ? sh[t - off] : 0;
        __syncthreads();
        sh[t] += u;
        __syncthreads();
    }
    g_blkoff[t] = sh[t] - v;   // exclusive
}

__global__ void k_scan3_dis() {
    int i = blockIdx.x * blockDim.x + threadIdx.x;
    if (i < NN) {
        int r = g_rowptr[i] + g_blkoff[i >> 10];
        g_rowptr[i] = r;
        g_cur[i] = r;
        g_dis[i] = rsqrtf(g_dis[i]);     // deg >= 1 (self-loop)
    }
}

// ---------------- scatter edges into CSR, norm computed inline ----------------
__global__ void k_scatter(const int* __restrict__ ei, const float* __restrict__ ew) {
    int e = blockIdx.x * blockDim.x + threadIdx.x;
    if (e >= EE) return;
    int s = ei[e], d = ei[EE + e];
    float nrm = g_dis[s] * ew[e] * g_dis[d];
    int pos = atomicAdd(&g_cur[d], 1);
    g_csr[pos] = make_int2(s, __float_as_int(nrm));
}

// ---------------- CSR gather aggregation (fp16 in, fp32 out): one warp/node --------
// Row = 64 halves = 128B = one cache line per gather.
__global__ void k_agg_csr_h(const __half* __restrict__ Xh, float* __restrict__ Out) {
    int warp = threadIdx.x >> 5;
    int lane = threadIdx.x & 31;
    int node = blockIdx.x * 8 + warp;
    const __half2* X2 = (const __half2*)Xh;

    float sn = g_dis[node];
    sn = sn * sn;
    float2 xs = __half22float2(X2[node * 32 + lane]);
    float2 acc = make_float2(sn * xs.x, sn * xs.y);

    int beg = g_rowptr[node];
    int end = beg + g_cnt[node];
    #pragma unroll 4
    for (int j = beg; j < end; j++) {
        int2 pr = g_csr[j];                            // uniform -> broadcast
        float nrm = __int_as_float(pr.y);
        float2 v = __half22float2(X2[pr.x * 32 + lane]); // 128B single-line gather
        acc.x = fmaf(nrm, v.x, acc.x);
        acc.y = fmaf(nrm, v.y, acc.y);
    }
    ((float2*)Out)[node * 32 + lane] = acc;
}

// ---------------- tf32 tensor-core GEMM: Y[N,NC] = X[N,K] @ W[K,NC] ----------------
__device__ __forceinline__ unsigned int cvt_tf32(float f) {
    unsigned int o;
    asm("cvt.rna.tf32.f32 %0, %1;" : "=r"(o) : "f"(f));
    return o;
}

__device__ __forceinline__ void mma_tf32(float* c, unsigned int a0, unsigned int a1,
                                         unsigned int a2, unsigned int a3,
                                         unsigned int b0, unsigned int b1) {
    asm volatile("mma.sync.aligned.m16n8k8.row.col.f32.tf32.tf32.f32 "
                 "{%0,%1,%2,%3}, {%4,%5,%6,%7}, {%8,%9}, {%0,%1,%2,%3};"
                 : "+f"(c[0]), "+f"(c[1]), "+f"(c[2]), "+f"(c[3])
                 : "r"(a0), "r"(a1), "r"(a2), "r"(a3), "r"(b0), "r"(b1));
}

// Block: 256 threads (8 warps), tile 128 rows x NC cols. Warp w owns rows [w*16, w*16+16).
// OUT_HALF: store __half2 (for h2t feeding the fp16 aggregation).
template<int K, int NC, bool BIAS_RELU, bool OUT_HALF>
__global__ void gemm_tc(const float* __restrict__ X, const float* __restrict__ W,
                        const float* __restrict__ bias, void* __restrict__ Yv) {
    constexpr int SX = K + 4;
    constexpr int SW = NC + 8;
    constexpr int NT = NC / 8;
    extern __shared__ float smem[];
    float* sX = smem;               // 128 * SX
    float* sW = smem + 128 * SX;    // K * SW

    int tid = threadIdx.x, lane = tid & 31, warp = tid >> 5;
    int row0 = blockIdx.x * 128;

    #pragma unroll 4
    for (int idx = tid; idx < 128 * (K / 4); idx += 256) {
        int r = idx / (K / 4);
        int c4 = idx % (K / 4);
        float4 v = ((const float4*)(X + (size_t)(row0 + r) * K))[c4];
        *(float4*)&sX[r * SX + c4 * 4] = v;
    }
    #pragma unroll 4
    for (int idx = tid; idx < K * (NC / 4); idx += 256) {
        int r = idx / (NC / 4);
        int c4 = idx % (NC / 4);
        float4 v = ((const float4*)(W + r * NC))[c4];
        *(float4*)&sW[r * SW + c4 * 4] = v;
    }
    __syncthreads();

    float acc[NT][4];
    #pragma unroll
    for (int t = 0; t < NT; t++)
        #pragma unroll
        for (int i = 0; i < 4; i++) acc[t][i] = 0.0f;

    int ar = warp * 16 + (lane >> 2);
    int ak = lane & 3;
    int bk = lane & 3;
    int bn = lane >> 2;

    #pragma unroll
    for (int ks = 0; ks < K / 8; ks++) {
        int k0 = ks * 8;
        unsigned int a0 = cvt_tf32(sX[ar * SX + k0 + ak]);
        unsigned int a1 = cvt_tf32(sX[(ar + 8) * SX + k0 + ak]);
        unsigned int a2 = cvt_tf32(sX[ar * SX + k0 + ak + 4]);
        unsigned int a3 = cvt_tf32(sX[(ar + 8) * SX + k0 + ak + 4]);
        #pragma unroll
        for (int t = 0; t < NT; t++) {
            unsigned int b0 = cvt_tf32(sW[(k0 + bk) * SW + t * 8 + bn]);
            unsigned int b1 = cvt_tf32(sW[(k0 + bk + 4) * SW + t * 8 + bn]);
            mma_tf32(acc[t], a0, a1, a2, a3, b0, b1);
        }
    }

    int orow = row0 + ar;
    #pragma unroll
    for (int t = 0; t < NT; t++) {
        int col = t * 8 + 2 * (lane & 3);
        float b0 = 0.f, b1 = 0.f;
        if (BIAS_RELU) { b0 = bias[col]; b1 = bias[col + 1]; }
        float2 v0 = make_float2(acc[t][0] + b0, acc[t][1] + b1);
        float2 v1 = make_float2(acc[t][2] + b0, acc[t][3] + b1);
        if (BIAS_RELU) {
            v0.x = fmaxf(v0.x, 0.f); v0.y = fmaxf(v0.y, 0.f);
            v1.x = fmaxf(v1.x, 0.f); v1.y = fmaxf(v1.y, 0.f);
        }
        if (OUT_HALF) {
            __half2* Y = (__half2*)Yv;
            Y[((size_t)orow * NC + col) / 2] = __floats2half2_rn(v0.x, v0.y);
            Y[((size_t)(orow + 8) * NC + col) / 2] = __floats2half2_rn(v1.x, v1.y);
        } else {
            float* Y = (float*)Yv;
            *(float2*)&Y[(size_t)orow * NC + col] = v0;
            *(float2*)&Y[(size_t)(orow + 8) * NC + col] = v1;
        }
    }
}

// ---------------- FC + softmax (fuses layer-2 bias + relu) ----------------
__global__ void fc_softmax(const float* __restrict__ H, const float* __restrict__ Wfc,
                           const float* __restrict__ bfc, const float* __restrict__ b2,
                           float* __restrict__ out) {
    int g = blockIdx.x;
    int tid = threadIdx.x;      // 256
    const float* hrow = H + g * 8192;

    float a0 = 0.f, a1 = 0.f, a2 = 0.f, a3 = 0.f;
    for (int j = tid; j < 8192; j += 256) {
        float v = hrow[j] + b2[j & 63];
        v = fmaxf(v, 0.f);
        float4 w = __ldg((const float4*)Wfc + j);
        a0 = fmaf(v, w.x, a0);
        a1 = fmaf(v, w.y, a1);
        a2 = fmaf(v, w.z, a2);
        a3 = fmaf(v, w.w, a3);
    }
    #pragma unroll
    for (int off = 16; off > 0; off >>= 1) {
        a0 += __shfl_xor_sync(0xffffffffu, a0, off);
        a1 += __shfl_xor_sync(0xffffffffu, a1, off);
        a2 += __shfl_xor_sync(0xffffffffu, a2, off);
        a3 += __shfl_xor_sync(0xffffffffu, a3, off);
    }
    __shared__ float sred[8][4];
    int lane = tid & 31, warp = tid >> 5;
    if (lane == 0) {
        sred[warp][0] = a0; sred[warp][1] = a1;
        sred[warp][2] = a2; sred[warp][3] = a3;
    }
    __syncthreads();
    if (tid == 0) {
        float l[4];
        #pragma unroll
        for (int c = 0; c < 4; c++) {
            float s = bfc[c];
            #pragma unroll
            for (int w = 0; w < 8; w++) s += sred[w][c];
            l[c] = s;
        }
        float m = fmaxf(fmaxf(l[0], l[1]), fmaxf(l[2], l[3]));
        float e0 = __expf(l[0] - m), e1 = __expf(l[1] - m);
        float e2 = __expf(l[2] - m), e3 = __expf(l[3] - m);
        float inv = 1.0f / (e0 + e1 + e2 + e3);
        out[g * 4 + 0] = e0 * inv;
        out[g * 4 + 1] = e1 * inv;
        out[g * 4 + 2] = e2 * inv;
        out[g * 4 + 3] = e3 * inv;
    }
}

// ---------------- launch ----------------
extern "C" void kernel_launch(void* const* d_in, const int* in_sizes, int n_in,
                              void* d_out, int out_size) {
    const float* x   = (const float*)d_in[0];
    const int*   ei  = (const int*)d_in[1];
    const float* ew  = (const float*)d_in[2];
    const float* W1  = (const float*)d_in[3];
    const float* b1  = (const float*)d_in[4];
    const float* W2  = (const float*)d_in[5];
    const float* b2  = (const float*)d_in[6];
    const float* Wfc = (const float*)d_in[7];
    const float* bfc = (const float*)d_in[8];
    float* out = (float*)d_out;

    __half* xh;  cudaGetSymbolAddress((void**)&xh, g_xh);
    float* aggx; cudaGetSymbolAddress((void**)&aggx, g_aggx);
    float* h1;   cudaGetSymbolAddress((void**)&h1, g_h1);
    __half* h2h; cudaGetSymbolAddress((void**)&h2h, g_h2h);
    float* h2;   cudaGetSymbolAddress((void**)&h2, g_h2);

    const int smem1 = (128 * 68 + 64 * 136) * 4;
    const int smem2 = (128 * 132 + 128 * 72) * 4;
    cudaFuncSetAttribute(gemm_tc<64, 128, true, false>,
                         cudaFuncAttributeMaxDynamicSharedMemorySize, smem1);
    cudaFuncSetAttribute(gemm_tc<128, 64, false, true>,
                         cudaFuncAttributeMaxDynamicSharedMemorySize, smem2);

    // normalization + CSR build (+ fp16 conversion of x, independent)
    k_init<<<NN / 256, 256>>>();
    k_deg_hist<<<EE / 256, 256>>>(ei, ew);
    k_x2h<<<NN * 16 / 256, 256>>>(x);
    k_scan1<<<128, 256>>>();
    k_scan2<<<1, 128>>>();
    k_scan3_dis<<<NN / 256, 256>>>();
    k_scatter<<<EE / 256, 256>>>(ei, ew);

    // layer 1: aggregate x (fp16 gathers), then TC GEMM (64->128) + bias + relu
    k_agg_csr_h<<<NN / 8, 256>>>(xh, aggx);
    gemm_tc<64, 128, true, false><<<NN / 128, 256, smem1>>>(aggx, W1, b1, h1);

    // layer 2: TC GEMM (128->64) -> fp16, then aggregate; bias/relu deferred to FC
    gemm_tc<128, 64, false, true><<<NN / 128, 256, smem2>>>(h1, W2, nullptr, h2h);
    k_agg_csr_h<<<NN / 8, 256>>>(h2h, h2);

    // FC + softmax
    fc_softmax<<<1024, 256>>>(h2, Wfc, bfc, b2, out);
}